// round 1
// baseline (speedup 1.0000x reference)
#include <cuda_runtime.h>

#define ULL unsigned long long

// Intermediate projections (b1 folded into g_ha). 512x768 fp32 each = 1.5 MB.
__device__ float g_ha[512 * 768];
__device__ float g_hb[512 * 768];

__device__ __forceinline__ ULL fma2(ULL a, ULL b, ULL c) {
    ULL d;
    asm("fma.rn.f32x2 %0, %1, %2, %3;" : "=l"(d) : "l"(a), "l"(b), "l"(c));
    return d;
}
__device__ __forceinline__ ULL add2(ULL a, ULL b) {
    ULL d;
    asm("add.rn.f32x2 %0, %1, %2;" : "=l"(d) : "l"(a), "l"(b));
    return d;
}

union F2U { ULL u; float2 f; };
union F4U { float4 f; ULL u[2]; float s[4]; };

// ---------------------------------------------------------------------------
// Kernel 1: projections.  C[m][n] = sum_k X[m][k] * W[k][n]  (+ b1 for z==0)
//   z=0: X=a (512x768), W=W1[0:768],    out=g_ha (bias folded)
//   z=1: X=b (512x768), W=W1[768:1536], out=g_hb
// Tiling: BM=64, BN=32, BK=32, 128 threads, per-thread 4m x 4n micro-tile.
// f32x2 packing over the M dimension (pairs contiguous in k-transposed smem),
// weights stored duplicated (dup(w),dup(w)) so no pack MOVs in the inner loop.
// Inner loop per kk: 2 LDS.64 (A pairs) + 4 LDS.64 (W dups) + 8 FFMA2.
// ---------------------------------------------------------------------------
__global__ __launch_bounds__(128) void proj_kernel(
    const float* __restrict__ A,
    const float* __restrict__ Bx,
    const float* __restrict__ W1,
    const float* __restrict__ b1)
{
    const int z = blockIdx.z;
    const float* __restrict__ X = z ? Bx : A;
    const float* __restrict__ W = W1 + (z ? 768 * 768 : 0);
    float* __restrict__ out = z ? g_hb : g_ha;

    const int m0 = blockIdx.x * 64;   // 512/64 = 8
    const int n0 = blockIdx.y * 32;   // 768/32 = 24

    // k-transposed X tile, padded to 66 floats/row (even => 8B aligned pairs,
    // 66 mod 32 = 2 spreads write banks).  W tile duplicated: [k][j][x] ulls.
    __shared__ __align__(16) float XsT[32][66];
    __shared__ ULL Wd[32 * 32];       // index k*32 + j*8 + x

    const int tid = threadIdx.x;
    const int tx = tid & 7;           // n-quad 0..7  (n = n0 + tx*4 + j)
    const int ty = tid >> 3;          // 0..15        (m = m0 + ty*4 + i)
    const int tm = ty * 4;

    ULL acc[2][4];
#pragma unroll
    for (int p = 0; p < 2; p++)
#pragma unroll
        for (int j = 0; j < 4; j++) acc[p][j] = 0ull;

    for (int kt = 0; kt < 768; kt += 32) {
        // --- load X tile (64 rows x 32 k), transpose into XsT ---
#pragma unroll
        for (int i = 0; i < 4; i++) {
            int q = tid + i * 128;            // 0..511
            int m = q >> 3, kc = q & 7;
            float4 v = *(const float4*)&X[(m0 + m) * 768 + kt + kc * 4];
            XsT[kc * 4 + 0][m] = v.x;
            XsT[kc * 4 + 1][m] = v.y;
            XsT[kc * 4 + 2][m] = v.z;
            XsT[kc * 4 + 3][m] = v.w;
        }
        // --- load W tile (32 k x 32 n), duplicated pairs ---
#pragma unroll
        for (int i = 0; i < 2; i++) {
            int q = tid + i * 128;            // 0..255
            int k = q >> 3, nc = q & 7;
            float4 v = *(const float4*)&W[(kt + k) * 768 + n0 + nc * 4];
            F2U d;
            d.f.x = v.x; d.f.y = v.x; Wd[k * 32 + 0  + nc] = d.u;
            d.f.x = v.y; d.f.y = v.y; Wd[k * 32 + 8  + nc] = d.u;
            d.f.x = v.z; d.f.y = v.z; Wd[k * 32 + 16 + nc] = d.u;
            d.f.x = v.w; d.f.y = v.w; Wd[k * 32 + 24 + nc] = d.u;
        }
        __syncthreads();

#pragma unroll
        for (int kk = 0; kk < 32; kk++) {
            ULL a0 = *(const ULL*)&XsT[kk][tm];       // rows (tm, tm+1)
            ULL a1 = *(const ULL*)&XsT[kk][tm + 2];   // rows (tm+2, tm+3)
#pragma unroll
            for (int j = 0; j < 4; j++) {
                ULL w = Wd[kk * 32 + j * 8 + tx];
                acc[0][j] = fma2(a0, w, acc[0][j]);
                acc[1][j] = fma2(a1, w, acc[1][j]);
            }
        }
        __syncthreads();
    }

    // --- epilogue: unpack, add bias (z==0), vectorized stores ---
    float4 bias = make_float4(0.f, 0.f, 0.f, 0.f);
    if (z == 0) bias = *(const float4*)&b1[n0 + tx * 4];

#pragma unroll
    for (int p = 0; p < 2; p++) {
        F2U u0, u1, u2, u3;
        u0.u = acc[p][0]; u1.u = acc[p][1]; u2.u = acc[p][2]; u3.u = acc[p][3];
        float4 rlo = make_float4(u0.f.x + bias.x, u1.f.x + bias.y,
                                 u2.f.x + bias.z, u3.f.x + bias.w);
        float4 rhi = make_float4(u0.f.y + bias.x, u1.f.y + bias.y,
                                 u2.f.y + bias.z, u3.f.y + bias.w);
        *(float4*)&out[(m0 + tm + 2 * p)     * 768 + n0 + tx * 4] = rlo;
        *(float4*)&out[(m0 + tm + 2 * p + 1) * 768 + n0 + tx * 4] = rhi;
    }
}

// ---------------------------------------------------------------------------
// Kernel 2: pairwise relu-reduce.
//   scores[b,s,t,o] = sum_h relu(g_ha[b,s,h] + g_hb[b,t,h]) * W2[h,o] + b2[o]
// Grid (4 b, 8 s-tiles of 16, 4 t-tiles of 32); 256 threads = 8 warps.
// Warp w owns s = s0+2w, s0+2w+1; lane owns t = t0+lane.
// hb transposed into smem [h-pair][t] (+1 ull pad) -> conflict-free lane reads;
// ha and W2 are 16B broadcast reads; f32x2 packing over the h dimension.
// h processed in 4 chunks of 192 to fit static smem (38.25 KB).
// ---------------------------------------------------------------------------
__global__ __launch_bounds__(256) void pair_kernel(
    const float* __restrict__ W2,
    const float* __restrict__ b2,
    float* __restrict__ out)
{
    const int b  = blockIdx.x;
    const int s0 = blockIdx.y * 16;
    const int t0 = blockIdx.z * 32;

    __shared__ __align__(16) float4 haI[8][96];   // [warp][hp] {sA h,h+1, sB h,h+1}
    __shared__ ULL hbs2[96][33];                  // [hp][t] = (hb[t][h], hb[t][h+1])
    __shared__ __align__(16) float4 wsI[96];      // {w0(h), w0(h+1), w1(h), w1(h+1)}

    const int tid  = threadIdx.x;
    const int w    = tid >> 5;
    const int lane = tid & 31;

    ULL acc00 = 0ull, acc01 = 0ull, acc10 = 0ull, acc11 = 0ull;

    for (int c = 0; c < 4; c++) {
        const int h0 = c * 192;

        // --- stage ha: 8 warps x 96 h-pairs ---
#pragma unroll
        for (int i = 0; i < 3; i++) {
            int q = tid + i * 256;                 // 0..767
            int ww = q / 96, hp = q % 96;
            int ra = b * 128 + s0 + 2 * ww;
            float2 fa = *(const float2*)&g_ha[ra * 768 + h0 + hp * 2];
            float2 fb = *(const float2*)&g_ha[(ra + 1) * 768 + h0 + hp * 2];
            haI[ww][hp] = make_float4(fa.x, fa.y, fb.x, fb.y);
        }
        // --- stage hb transposed: 32 t x 48 float4 ---
#pragma unroll
        for (int i = 0; i < 6; i++) {
            int q = tid + i * 256;                 // 0..1535
            int t = q / 48, cq = q % 48;
            float4 v = *(const float4*)&g_hb[(b * 128 + t0 + t) * 768 + h0 + cq * 4];
            F2U d0; d0.f.x = v.x; d0.f.y = v.y;
            F2U d1; d1.f.x = v.z; d1.f.y = v.w;
            hbs2[cq * 2 + 0][t] = d0.u;
            hbs2[cq * 2 + 1][t] = d1.u;
        }
        // --- stage W2 pairs ---
        if (tid < 96) {
            float4 v = *(const float4*)&W2[(h0 + tid * 2) * 2];
            wsI[tid] = make_float4(v.x, v.z, v.y, v.w);
        }
        __syncthreads();

#pragma unroll 8
        for (int hp = 0; hp < 96; hp++) {
            F4U av; av.f = haI[w][hp];
            ULL vb = hbs2[hp][lane];
            F4U wv; wv.f = wsI[hp];

            F2U x0; x0.u = add2(av.u[0], vb);
            x0.f.x = fmaxf(x0.f.x, 0.f);
            x0.f.y = fmaxf(x0.f.y, 0.f);
            F2U x1; x1.u = add2(av.u[1], vb);
            x1.f.x = fmaxf(x1.f.x, 0.f);
            x1.f.y = fmaxf(x1.f.y, 0.f);

            acc00 = fma2(x0.u, wv.u[0], acc00);
            acc01 = fma2(x0.u, wv.u[1], acc01);
            acc10 = fma2(x1.u, wv.u[0], acc10);
            acc11 = fma2(x1.u, wv.u[1], acc11);
        }
        __syncthreads();
    }

    const float bb0 = b2[0], bb1 = b2[1];
    F2U r0, r1, r2, r3;
    r0.u = acc00; r1.u = acc01; r2.u = acc10; r3.u = acc11;

    const int t  = t0 + lane;
    const int sA = s0 + 2 * w;
    float2 oA = make_float2(r0.f.x + r0.f.y + bb0, r1.f.x + r1.f.y + bb1);
    float2 oB = make_float2(r2.f.x + r2.f.y + bb0, r3.f.x + r3.f.y + bb1);
    *(float2*)&out[((b * 128 + sA)     * 128 + t) * 2] = oA;
    *(float2*)&out[((b * 128 + sA + 1) * 128 + t) * 2] = oB;
}

// ---------------------------------------------------------------------------
extern "C" void kernel_launch(void* const* d_in, const int* in_sizes, int n_in,
                              void* d_out, int out_size)
{
    const float* a  = (const float*)d_in[0];   // (4,128,768)
    const float* bx = (const float*)d_in[1];   // (4,128,768)
    const float* W1 = (const float*)d_in[2];   // (1536,768)
    const float* b1 = (const float*)d_in[3];   // (768,)
    const float* W2 = (const float*)d_in[4];   // (768,2)
    const float* b2 = (const float*)d_in[5];   // (2,)
    float* out = (float*)d_out;                // (4,128,128,2)

    proj_kernel<<<dim3(8, 24, 2), 128>>>(a, bx, W1, b1);
    pair_kernel<<<dim3(4, 8, 4), 256>>>(W2, b2, out);
}

// round 2
// speedup vs baseline: 1.1076x; 1.1076x over previous
#include <cuda_runtime.h>

#define ULL unsigned long long

// Intermediate projections (b1 folded later). 512x768 fp32 each = 1.5 MB.
__device__ float g_ha[512 * 768];
__device__ float g_hb[512 * 768];

__device__ __forceinline__ ULL fma2(ULL a, ULL b, ULL c) {
    ULL d;
    asm("fma.rn.f32x2 %0, %1, %2, %3;" : "=l"(d) : "l"(a), "l"(b), "l"(c));
    return d;
}
__device__ __forceinline__ ULL add2(ULL a, ULL b) {
    ULL d;
    asm("add.rn.f32x2 %0, %1, %2;" : "=l"(d) : "l"(a), "l"(b));
    return d;
}
__device__ __forceinline__ ULL dup2(float a) {
    ULL d;
    unsigned r = __float_as_uint(a);
    asm("mov.b64 %0, {%1, %1};" : "=l"(d) : "r"(r));
    return d;
}

union F2U { ULL u; float2 f; };
union F4U { float4 f; ULL u[2]; float s[4]; };

// ---------------------------------------------------------------------------
// Kernel 1: projections.  C[m][n] = sum_k X[m][k] * W[k][n]  (+ b1 for z==0)
// BM=64, BN=32, BK=32, 128 threads, microtile 4m x 4n, n-packed f32x2 accs.
// Double-buffered smem with register prefetch; ONE __syncthreads per kt.
// Per kk per thread: 4 LDS.32 (A, conflict-free, bcast x8) + 4 dup-MOV (alu)
//                    + 1 LDS.128 (W pairs) + 8 FFMA2  -> fma-pipe bound.
// ---------------------------------------------------------------------------
__global__ __launch_bounds__(128) void proj_kernel(
    const float* __restrict__ A,
    const float* __restrict__ Bx,
    const float* __restrict__ W1,
    const float* __restrict__ b1)
{
    const int z = blockIdx.z;
    const float* __restrict__ X = z ? Bx : A;
    const float* __restrict__ W = W1 + (z ? 768 * 768 : 0);
    float* __restrict__ out = z ? g_hb : g_ha;

    const int m0 = blockIdx.x * 64;   // 512/64 = 8
    const int n0 = blockIdx.y * 32;   // 768/32 = 24

    // Xs: [m][k] stride 33 (scalar access; banks (m+4kc+c)%32 all distinct)
    // Ws: [k][n] stride 36 (16B-aligned rows for LDS.128)
    __shared__ float Xs[2][64][33];
    __shared__ __align__(16) float Ws[2][32][36];

    const int tid = threadIdx.x;
    const int tx = tid & 7;           // n = n0 + tx*4 + {0..3}
    const int ty = tid >> 3;          // 0..15
    const int tm = ty * 4;            // rows tm..tm+3

    ULL acc[4][2];
#pragma unroll
    for (int i = 0; i < 4; i++) { acc[i][0] = 0ull; acc[i][1] = 0ull; }

    float4 xr[4];   // X prefetch: 64x32 floats / 128 thr = 4 float4
    float4 wr[2];   // W prefetch: 32x32 floats / 128 thr = 2 float4

    // ---- prologue: load tile 0 ----
#pragma unroll
    for (int j = 0; j < 4; j++) {
        int q = tid + j * 128;            // 0..511
        int m = q >> 3, kc = q & 7;
        xr[j] = *(const float4*)&X[(m0 + m) * 768 + kc * 4];
    }
#pragma unroll
    for (int j = 0; j < 2; j++) {
        int q = tid + j * 128;            // 0..255
        int k = q >> 3, nc = q & 7;
        wr[j] = *(const float4*)&W[k * 768 + n0 + nc * 4];
    }
#pragma unroll
    for (int j = 0; j < 4; j++) {
        int q = tid + j * 128;
        int m = q >> 3, kc = q & 7;
        Xs[0][m][kc * 4 + 0] = xr[j].x;
        Xs[0][m][kc * 4 + 1] = xr[j].y;
        Xs[0][m][kc * 4 + 2] = xr[j].z;
        Xs[0][m][kc * 4 + 3] = xr[j].w;
    }
#pragma unroll
    for (int j = 0; j < 2; j++) {
        int q = tid + j * 128;
        int k = q >> 3, nc = q & 7;
        *(float4*)&Ws[0][k][nc * 4] = wr[j];
    }

    for (int kt = 0; kt < 24; kt++) {
        const int st = kt & 1;
        // prefetch next tile into registers (overlaps barrier + compute)
        if (kt < 23) {
            const int kb = (kt + 1) * 32;
#pragma unroll
            for (int j = 0; j < 4; j++) {
                int q = tid + j * 128;
                int m = q >> 3, kc = q & 7;
                xr[j] = *(const float4*)&X[(m0 + m) * 768 + kb + kc * 4];
            }
#pragma unroll
            for (int j = 0; j < 2; j++) {
                int q = tid + j * 128;
                int k = q >> 3, nc = q & 7;
                wr[j] = *(const float4*)&W[(kb + k) * 768 + n0 + nc * 4];
            }
        }
        __syncthreads();   // buf[st] stores visible; all readers of buf[st^1] done

#pragma unroll 8
        for (int kk = 0; kk < 32; kk++) {
            ULL a0 = dup2(Xs[st][tm + 0][kk]);
            ULL a1 = dup2(Xs[st][tm + 1][kk]);
            ULL a2 = dup2(Xs[st][tm + 2][kk]);
            ULL a3 = dup2(Xs[st][tm + 3][kk]);
            F4U w; w.f = *(const float4*)&Ws[st][kk][tx * 4];
            acc[0][0] = fma2(a0, w.u[0], acc[0][0]);
            acc[0][1] = fma2(a0, w.u[1], acc[0][1]);
            acc[1][0] = fma2(a1, w.u[0], acc[1][0]);
            acc[1][1] = fma2(a1, w.u[1], acc[1][1]);
            acc[2][0] = fma2(a2, w.u[0], acc[2][0]);
            acc[2][1] = fma2(a2, w.u[1], acc[2][1]);
            acc[3][0] = fma2(a3, w.u[0], acc[3][0]);
            acc[3][1] = fma2(a3, w.u[1], acc[3][1]);
        }

        if (kt < 23) {
            const int ns = st ^ 1;
#pragma unroll
            for (int j = 0; j < 4; j++) {
                int q = tid + j * 128;
                int m = q >> 3, kc = q & 7;
                Xs[ns][m][kc * 4 + 0] = xr[j].x;
                Xs[ns][m][kc * 4 + 1] = xr[j].y;
                Xs[ns][m][kc * 4 + 2] = xr[j].z;
                Xs[ns][m][kc * 4 + 3] = xr[j].w;
            }
#pragma unroll
            for (int j = 0; j < 2; j++) {
                int q = tid + j * 128;
                int k = q >> 3, nc = q & 7;
                *(float4*)&Ws[ns][k][nc * 4] = wr[j];
            }
        }
    }

    // ---- epilogue: bias (z==0) + vectorized stores ----
    F4U bv; bv.f = make_float4(0.f, 0.f, 0.f, 0.f);
    if (z == 0) bv.f = *(const float4*)&b1[n0 + tx * 4];

#pragma unroll
    for (int i = 0; i < 4; i++) {
        F4U r;
        r.u[0] = add2(acc[i][0], bv.u[0]);
        r.u[1] = add2(acc[i][1], bv.u[1]);
        *(float4*)&out[(m0 + tm + i) * 768 + n0 + tx * 4] = r.f;
    }
}

// ---------------------------------------------------------------------------
// Kernel 2: pairwise relu-reduce.
//   scores[b,s,t,o] = sum_h relu(g_ha[b,s,h] + g_hb[b,t,h]) * W2[h,o] + b2[o]
// Grid (4 b, 16 s-tiles of 8, 4 t-tiles of 32); 256 threads = 8 warps.
// Warp w owns s = s0+w; lane owns t = t0+lane. h in 4 chunks of 192.
// Per hp per warp: 2 broadcast LDS + 1 lane LDS.64 + add2 + 2 max + 2 fma2.
// ---------------------------------------------------------------------------
__global__ __launch_bounds__(256) void pair_kernel(
    const float* __restrict__ W2,
    const float* __restrict__ b2,
    float* __restrict__ out)
{
    const int b  = blockIdx.x;
    const int s0 = blockIdx.y * 8;
    const int t0 = blockIdx.z * 32;

    __shared__ ULL haS[8][96];                    // [s][hp]
    __shared__ ULL hbT[96][33];                   // [hp][t], 2-phase min reads
    __shared__ __align__(16) float4 ws[96];       // {w0(h),w0(h+1),w1(h),w1(h+1)}

    const int tid  = threadIdx.x;
    const int w    = tid >> 5;
    const int lane = tid & 31;

    ULL acc0 = 0ull, acc1 = 0ull;

    for (int c = 0; c < 4; c++) {
        const int h0 = c * 192;

        // stage ha: 768 ULL / 256 thr = 3 each
#pragma unroll
        for (int i = 0; i < 3; i++) {
            int q = tid + i * 256;
            int ss = q / 96, hp = q % 96;
            haS[ss][hp] = *(const ULL*)&g_ha[(b * 128 + s0 + ss) * 768 + h0 + 2 * hp];
        }
        // stage hb transposed: 3072 ULL / 256 thr = 12 each
#pragma unroll
        for (int i = 0; i < 12; i++) {
            int q = tid + i * 256;
            int t = q / 96, hp = q % 96;
            hbT[hp][t] = *(const ULL*)&g_hb[(b * 128 + t0 + t) * 768 + h0 + 2 * hp];
        }
        // stage W2 pairs (rearranged so f32x2 pairs are over h)
        if (tid < 96) {
            float4 v = *(const float4*)&W2[(h0 + 2 * tid) * 2];
            ws[tid] = make_float4(v.x, v.z, v.y, v.w);
        }
        __syncthreads();

#pragma unroll 8
        for (int hp = 0; hp < 96; hp++) {
            ULL va = haS[w][hp];
            ULL vb = hbT[hp][lane];
            F4U wv; wv.f = ws[hp];
            F2U x; x.u = add2(va, vb);
            x.f.x = fmaxf(x.f.x, 0.f);
            x.f.y = fmaxf(x.f.y, 0.f);
            acc0 = fma2(x.u, wv.u[0], acc0);
            acc1 = fma2(x.u, wv.u[1], acc1);
        }
        __syncthreads();
    }

    F2U r0, r1; r0.u = acc0; r1.u = acc1;
    const int s = s0 + w;
    const int t = t0 + lane;
    float2 o = make_float2(r0.f.x + r0.f.y + b2[0], r1.f.x + r1.f.y + b2[1]);
    *(float2*)&out[((b * 128 + s) * 128 + t) * 2] = o;
}

// ---------------------------------------------------------------------------
extern "C" void kernel_launch(void* const* d_in, const int* in_sizes, int n_in,
                              void* d_out, int out_size)
{
    const float* a  = (const float*)d_in[0];   // (4,128,768)
    const float* bx = (const float*)d_in[1];   // (4,128,768)
    const float* W1 = (const float*)d_in[2];   // (1536,768)
    const float* b1 = (const float*)d_in[3];   // (768,)
    const float* W2 = (const float*)d_in[4];   // (768,2)
    const float* b2 = (const float*)d_in[5];   // (2,)
    float* out = (float*)d_out;                // (4,128,128,2)

    proj_kernel<<<dim3(8, 24, 2), 128>>>(a, bx, W1, b1);
    pair_kernel<<<dim3(4, 16, 4), 256>>>(W2, b2, out);
}

// round 3
// speedup vs baseline: 2.3305x; 2.1040x over previous
#include <cuda_runtime.h>
#include <cstdint>

#define ULL unsigned long long

__device__ float g_ha[512 * 768];
__device__ float g_hb[512 * 768];

__device__ __forceinline__ ULL fma2(ULL a, ULL b, ULL c) {
    ULL d;
    asm("fma.rn.f32x2 %0, %1, %2, %3;" : "=l"(d) : "l"(a), "l"(b), "l"(c));
    return d;
}
__device__ __forceinline__ ULL add2(ULL a, ULL b) {
    ULL d;
    asm("add.rn.f32x2 %0, %1, %2;" : "=l"(d) : "l"(a), "l"(b));
    return d;
}

union F2U { ULL u; float2 f; };
union F4U { float4 f; ULL u[2]; float s[4]; uint4 q; };

// ---------------------------------------------------------------------------
// Kernel 1: projections, K-packed f32x2.
//   acc[i][j] (ULL) holds (even-k partial, odd-k partial); both FFMA2 operands
//   are natural k-pairs -> no operand duplication. Horizontal add at the end.
// BM=64, BN=32, BK=32, 128 threads, microtile 4m x 4n.
// Smem lines are 16B k-quads with XOR-swizzled line indices:
//   Xs line for (m,kc):  16*(m&3) + ((m>>2) ^ kc)   (reader: 16*i + (ty^kc))
//   Ws line for (n,kc):  8*(n&3)  + (n>>2)          (reader: 8*j + tx)
// All inner-loop LDS.128 are single-wavefront; STS at their 4-phase floor.
// Per 4 k's: 8 LDS.128 + 32 FFMA2  (80% fma fraction).
// ---------------------------------------------------------------------------
__global__ __launch_bounds__(128) void proj_kernel(
    const float* __restrict__ A,
    const float* __restrict__ Bx,
    const float* __restrict__ W1,
    const float* __restrict__ b1)
{
    const int z = blockIdx.z;
    const float* __restrict__ X = z ? Bx : A;
    const float* __restrict__ W = W1 + (z ? 768 * 768 : 0);
    float* __restrict__ out = z ? g_hb : g_ha;

    const int m0 = blockIdx.x * 64;   // 8
    const int n0 = blockIdx.y * 32;   // 24

    __shared__ uint4 Xs[2][8][64];    // [buf][kc][line]
    __shared__ uint4 Ws[2][8][32];

    const int tid = threadIdx.x;
    const int tx = tid & 7;           // n = n0 + 4*tx + j
    const int ty = tid >> 3;          // m = m0 + 4*ty + i   (ty 0..15)

    ULL acc[4][4];
#pragma unroll
    for (int i = 0; i < 4; i++)
#pragma unroll
        for (int j = 0; j < 4; j++) acc[i][j] = 0ull;

    float4 xr[4], wr[2];

    // ---- prologue: load + store tile 0 ----
#pragma unroll
    for (int j = 0; j < 4; j++) {
        int q = tid + j * 128;            // 0..511
        int m = q >> 3, kc = q & 7;
        xr[j] = *(const float4*)&X[(m0 + m) * 768 + kc * 4];
    }
#pragma unroll
    for (int j = 0; j < 2; j++) {
        int q = tid + j * 128;            // 0..255
        int k = q >> 3, nc = q & 7;
        wr[j] = *(const float4*)&W[k * 768 + n0 + nc * 4];
    }
#pragma unroll
    for (int j = 0; j < 4; j++) {
        int q = tid + j * 128;
        int m = q >> 3, kc = q & 7;
        int line = 16 * (m & 3) + ((m >> 2) ^ kc);
        F4U v; v.f = xr[j];
        Xs[0][kc][line] = v.q;
    }
#pragma unroll
    for (int j = 0; j < 2; j++) {
        int q = tid + j * 128;
        int k = q >> 3, nc = q & 7;
        float* base = (float*)&Ws[0][k >> 2][0];
        int e = k & 3;
        base[(8 * 0 + nc) * 4 + e] = wr[j].x;
        base[(8 * 1 + nc) * 4 + e] = wr[j].y;
        base[(8 * 2 + nc) * 4 + e] = wr[j].z;
        base[(8 * 3 + nc) * 4 + e] = wr[j].w;
    }

    for (int kt = 0; kt < 24; kt++) {
        const int st = kt & 1;
        if (kt < 23) {
            const int kb = (kt + 1) * 32;
#pragma unroll
            for (int j = 0; j < 4; j++) {
                int q = tid + j * 128;
                int m = q >> 3, kc = q & 7;
                xr[j] = *(const float4*)&X[(m0 + m) * 768 + kb + kc * 4];
            }
#pragma unroll
            for (int j = 0; j < 2; j++) {
                int q = tid + j * 128;
                int k = q >> 3, nc = q & 7;
                wr[j] = *(const float4*)&W[(kb + k) * 768 + n0 + nc * 4];
            }
        }
        __syncthreads();

#pragma unroll
        for (int kc = 0; kc < 8; kc++) {
            F4U a_[4], w_[4];
#pragma unroll
            for (int i = 0; i < 4; i++)
                a_[i].q = Xs[st][kc][16 * i + (ty ^ kc)];
#pragma unroll
            for (int j = 0; j < 4; j++)
                w_[j].q = Ws[st][kc][8 * j + tx];
#pragma unroll
            for (int i = 0; i < 4; i++)
#pragma unroll
                for (int j = 0; j < 4; j++) {
                    acc[i][j] = fma2(a_[i].u[0], w_[j].u[0], acc[i][j]);
                    acc[i][j] = fma2(a_[i].u[1], w_[j].u[1], acc[i][j]);
                }
        }

        if (kt < 23) {
            const int ns = st ^ 1;
#pragma unroll
            for (int j = 0; j < 4; j++) {
                int q = tid + j * 128;
                int m = q >> 3, kc = q & 7;
                int line = 16 * (m & 3) + ((m >> 2) ^ kc);
                F4U v; v.f = xr[j];
                Xs[ns][kc][line] = v.q;
            }
#pragma unroll
            for (int j = 0; j < 2; j++) {
                int q = tid + j * 128;
                int k = q >> 3, nc = q & 7;
                float* base = (float*)&Ws[ns][k >> 2][0];
                int e = k & 3;
                base[(8 * 0 + nc) * 4 + e] = wr[j].x;
                base[(8 * 1 + nc) * 4 + e] = wr[j].y;
                base[(8 * 2 + nc) * 4 + e] = wr[j].z;
                base[(8 * 3 + nc) * 4 + e] = wr[j].w;
            }
        }
    }

    // ---- epilogue: horizontal add + bias (z==0) ----
    float4 bv = make_float4(0.f, 0.f, 0.f, 0.f);
    if (z == 0) bv = *(const float4*)&b1[n0 + 4 * tx];

#pragma unroll
    for (int i = 0; i < 4; i++) {
        F2U c0, c1, c2, c3;
        c0.u = acc[i][0]; c1.u = acc[i][1]; c2.u = acc[i][2]; c3.u = acc[i][3];
        float4 r = make_float4(c0.f.x + c0.f.y + bv.x,
                               c1.f.x + c1.f.y + bv.y,
                               c2.f.x + c2.f.y + bv.z,
                               c3.f.x + c3.f.y + bv.w);
        *(float4*)&out[(m0 + 4 * ty + i) * 768 + n0 + 4 * tx] = r;
    }
}

// ---------------------------------------------------------------------------
// Kernel 2: pairwise relu-reduce.
//   scores[b,s,t,o] = sum_h relu(g_ha[b,s,h] + g_hb[b,t,h]) * W2[h,o] + b2[o]
// Grid (4 b, 8 s-tiles of 16, 4 t-tiles of 32) = 128 blocks (1/SM), 8 warps.
// Warp w owns s = s0+2w, s0+2w+1; lane owns t = t0+lane.
// h in 8 chunks of 96, double-buffered with register prefetch, 1 sync/chunk.
// Per h-pair: 1 LDS.128 ha(2s, broadcast) + 1 LDS.64 hb + 1 LDS.128 W2
//             + 2 add2 + 4 FMNMX + 4 fma2 = 13 instr for 64 outputs' partials.
// ---------------------------------------------------------------------------
__global__ __launch_bounds__(256) void pair_kernel(
    const float* __restrict__ W2,
    const float* __restrict__ b2,
    float* __restrict__ out)
{
    const int b  = blockIdx.x;
    const int s0 = blockIdx.y * 16;
    const int t0 = blockIdx.z * 32;

    __shared__ __align__(16) float4 haS[2][8][48];  // [buf][warp][hp] (sa,sa',sb,sb')
    __shared__ ULL hbT[2][48][33];                  // [buf][hp][t]
    __shared__ __align__(16) float4 wsS[2][48];     // (w0(h),w0(h+1),w1(h),w1(h+1))

    const int tid  = threadIdx.x;
    const int w    = tid >> 5;
    const int lane = tid & 31;

    // staging index precompute (chunk-invariant)
    const unsigned e0w = (unsigned)tid / 48u, e0p = (unsigned)tid % 48u;
    const unsigned e1 = (unsigned)tid + 256u;
    const unsigned e1w = e1 / 48u, e1p = e1 % 48u;   // valid iff tid < 128
    unsigned tq[3], hq[3];
#pragma unroll
    for (int i = 0; i < 3; i++) {
        unsigned q = (unsigned)tid + 256u * i;       // 0..767
        tq[i] = q / 24u; hq[i] = q % 24u;
    }

    ULL a00 = 0ull, a01 = 0ull, a10 = 0ull, a11 = 0ull;

    float2 pa0[2], pa1[2];
    float4 pb[3];
    float4 pw;

    // ---- LOAD chunk 0 ----
    {
        const int h0 = 0;
        pa0[0] = *(const float2*)&g_ha[(b * 128 + s0 + 2 * e0w) * 768 + h0 + 2 * e0p];
        pa0[1] = *(const float2*)&g_ha[(b * 128 + s0 + 2 * e0w + 1) * 768 + h0 + 2 * e0p];
        if (tid < 128) {
            pa1[0] = *(const float2*)&g_ha[(b * 128 + s0 + 2 * e1w) * 768 + h0 + 2 * e1p];
            pa1[1] = *(const float2*)&g_ha[(b * 128 + s0 + 2 * e1w + 1) * 768 + h0 + 2 * e1p];
        }
#pragma unroll
        for (int i = 0; i < 3; i++)
            pb[i] = *(const float4*)&g_hb[(b * 128 + t0 + tq[i]) * 768 + h0 + hq[i] * 4];
        if (tid < 48) pw = *(const float4*)&W2[(h0 + 2 * tid) * 2];
    }
    // ---- STORE chunk 0 ----
    {
        haS[0][e0w][e0p] = make_float4(pa0[0].x, pa0[0].y, pa0[1 - 1].x * 0.f + pa0[1].x, pa0[1].y);
        // (written cleanly below; overwrite to avoid confusion)
        haS[0][e0w][e0p] = make_float4(pa0[0].x, pa0[0].y, pa0[1].x, pa0[1].y);
        if (tid < 128)
            haS[0][e1w][e1p] = make_float4(pa1[0].x, pa1[0].y, pa1[1].x, pa1[1].y);
#pragma unroll
        for (int i = 0; i < 3; i++) {
            F2U d0; d0.f.x = pb[i].x; d0.f.y = pb[i].y;
            F2U d1; d1.f.x = pb[i].z; d1.f.y = pb[i].w;
            hbT[0][2 * hq[i] + 0][tq[i]] = d0.u;
            hbT[0][2 * hq[i] + 1][tq[i]] = d1.u;
        }
        if (tid < 48) wsS[0][tid] = make_float4(pw.x, pw.z, pw.y, pw.w);
    }

    for (int c = 0; c < 8; c++) {
        const int buf = c & 1;
        if (c < 7) {
            const int h0 = (c + 1) * 96;
            pa0[0] = *(const float2*)&g_ha[(b * 128 + s0 + 2 * e0w) * 768 + h0 + 2 * e0p];
            pa0[1] = *(const float2*)&g_ha[(b * 128 + s0 + 2 * e0w + 1) * 768 + h0 + 2 * e0p];
            if (tid < 128) {
                pa1[0] = *(const float2*)&g_ha[(b * 128 + s0 + 2 * e1w) * 768 + h0 + 2 * e1p];
                pa1[1] = *(const float2*)&g_ha[(b * 128 + s0 + 2 * e1w + 1) * 768 + h0 + 2 * e1p];
            }
#pragma unroll
            for (int i = 0; i < 3; i++)
                pb[i] = *(const float4*)&g_hb[(b * 128 + t0 + tq[i]) * 768 + h0 + hq[i] * 4];
            if (tid < 48) pw = *(const float4*)&W2[(h0 + 2 * tid) * 2];
        }
        __syncthreads();

#pragma unroll 12
        for (int hp = 0; hp < 48; hp++) {
            F4U av; av.f = haS[buf][w][hp];
            ULL vb = hbT[buf][hp][lane];
            F4U wv; wv.f = wsS[buf][hp];

            F2U x0; x0.u = add2(av.u[0], vb);
            x0.f.x = fmaxf(x0.f.x, 0.f);
            x0.f.y = fmaxf(x0.f.y, 0.f);
            F2U x1; x1.u = add2(av.u[1], vb);
            x1.f.x = fmaxf(x1.f.x, 0.f);
            x1.f.y = fmaxf(x1.f.y, 0.f);

            a00 = fma2(x0.u, wv.u[0], a00);
            a01 = fma2(x0.u, wv.u[1], a01);
            a10 = fma2(x1.u, wv.u[0], a10);
            a11 = fma2(x1.u, wv.u[1], a11);
        }

        if (c < 7) {
            const int nb = buf ^ 1;
            haS[nb][e0w][e0p] = make_float4(pa0[0].x, pa0[0].y, pa0[1].x, pa0[1].y);
            if (tid < 128)
                haS[nb][e1w][e1p] = make_float4(pa1[0].x, pa1[0].y, pa1[1].x, pa1[1].y);
#pragma unroll
            for (int i = 0; i < 3; i++) {
                F2U d0; d0.f.x = pb[i].x; d0.f.y = pb[i].y;
                F2U d1; d1.f.x = pb[i].z; d1.f.y = pb[i].w;
                hbT[nb][2 * hq[i] + 0][tq[i]] = d0.u;
                hbT[nb][2 * hq[i] + 1][tq[i]] = d1.u;
            }
            if (tid < 48) wsS[nb][tid] = make_float4(pw.x, pw.z, pw.y, pw.w);
        }
    }

    const float bb0 = b2[0], bb1 = b2[1];
    F2U r00, r01, r10, r11;
    r00.u = a00; r01.u = a01; r10.u = a10; r11.u = a11;

    const int sa = s0 + 2 * w;
    const int t  = t0 + lane;
    float2 oA = make_float2(r00.f.x + r00.f.y + bb0, r01.f.x + r01.f.y + bb1);
    float2 oB = make_float2(r10.f.x + r10.f.y + bb0, r11.f.x + r11.f.y + bb1);
    *(float2*)&out[((b * 128 + sa)     * 128 + t) * 2] = oA;
    *(float2*)&out[((b * 128 + sa + 1) * 128 + t) * 2] = oB;
}

// ---------------------------------------------------------------------------
extern "C" void kernel_launch(void* const* d_in, const int* in_sizes, int n_in,
                              void* d_out, int out_size)
{
    const float* a  = (const float*)d_in[0];   // (4,128,768)
    const float* bx = (const float*)d_in[1];   // (4,128,768)
    const float* W1 = (const float*)d_in[2];   // (1536,768)
    const float* b1 = (const float*)d_in[3];   // (768,)
    const float* W2 = (const float*)d_in[4];   // (768,2)
    const float* b2 = (const float*)d_in[5];   // (2,)
    float* out = (float*)d_out;                // (4,128,128,2)

    proj_kernel<<<dim3(8, 24, 2), 128>>>(a, bx, W1, b1);
    pair_kernel<<<dim3(4, 8, 4), 256>>>(W2, b2, out);
}